// round 3
// baseline (speedup 1.0000x reference)
#include <cuda_runtime.h>
#include <math.h>

#define NR   32768
#define DIM  512
#define KCODE 8192
#define DECAY 0.99f
#define ONE_MINUS_DECAY 0.01f
#define EPS 1e-5f

// ---------------- scratch (__device__ globals; no allocation) ----------------
static __device__ __align__(256) float  g_flat[NR * DIM];      // normalized inputs (64 MB)
static __device__ __align__(256) float  g_embn[KCODE * DIM];   // normalized embedding (16 MB)
static __device__ int    g_idx[NR];
static __device__ float  g_counts[KCODE];
static __device__ __align__(256) float  g_dw[KCODE * DIM];     // scatter accumulator (16 MB)
static __device__ double g_loss;
static __device__ float  g_newcs[KCODE];

// ---------------- output layout (float32, concatenated in return order) -----
// quantized_st  [8,4096,512] : 16777216 @ 0
// loss          scalar       : 1        @ 16777216
// encoding_idx  [8,4096]     : 32768    @ 16777217
// new_cs        [8192]       : 8192     @ 16809985
// new_ema_w     [8192,512]   : 4194304  @ 16818177   (odd offset -> scalar stores!)
// new_embedding [8192,512]   : 4194304  @ 21012481   (odd offset -> scalar stores!)
#define OFF_LOSS 16777216
#define OFF_IDX  16777217
#define OFF_CS   16809985
#define OFF_W    16818177
#define OFF_EMB  21012481

// ---------------- packed f32x2 helpers ----------------
#define FMA2(d, a, b) asm("fma.rn.f32x2 %0, %1, %2, %0;" : "+l"(d) : "l"(a), "l"(b))
#define PACK2(d, x, y) asm("mov.b64 %0, {%1, %2};" : "=l"(d) : "f"(x), "f"(y))
#define UNPACK2(lo, hi, v) asm("mov.b64 {%0, %1}, %2;" : "=f"(lo), "=f"(hi) : "l"(v))

// ---------------- kernels ----------------
__global__ void k_zero() {
    int i = blockIdx.x * blockDim.x + threadIdx.x;
    int stride = gridDim.x * blockDim.x;
    float4 z = make_float4(0.f, 0.f, 0.f, 0.f);
    int tot4 = KCODE * DIM / 4;
    for (int j = i; j < tot4; j += stride) ((float4*)g_dw)[j] = z;
    for (int j = i; j < KCODE; j += stride) g_counts[j] = 0.f;
    if (i == 0) g_loss = 0.0;
}

// which==0: inputs -> g_flat ; which==1: embedding -> g_embn
__global__ void k_norm(const float* __restrict__ src, int which) {
    int row = blockIdx.x;
    int t = threadIdx.x;  // 128 threads, 4 floats each
    const float4* s = (const float4*)(src + (size_t)row * DIM);
    float4 v = s[t];
    float ss = v.x * v.x + v.y * v.y + v.z * v.z + v.w * v.w;
    #pragma unroll
    for (int o = 16; o; o >>= 1) ss += __shfl_xor_sync(0xFFFFFFFFu, ss, o);
    __shared__ float wsum[4];
    if ((t & 31) == 0) wsum[t >> 5] = ss;
    __syncthreads();
    float tot = wsum[0] + wsum[1] + wsum[2] + wsum[3];
    float inv = 1.0f / fmaxf(sqrtf(tot), 1e-12f);
    float4 o4 = make_float4(v.x * inv, v.y * inv, v.z * inv, v.w * inv);
    float* dst = which ? g_embn : g_flat;
    ((float4*)(dst + (size_t)row * DIM))[t] = o4;
}

// GEMM-argmax: CTA = 128 rows; loops codes in chunks of 128; exact fp32 via f32x2 FMA.
__global__ __launch_bounds__(256, 2) void k_argmax(float* __restrict__ idx_out) {
    __shared__ float As[16][132];   // [k][row]
    __shared__ float Bs[16][132];   // [k][code]
    __shared__ float cv[128][17];
    __shared__ int   ci[128][17];
    __shared__ float rv[128];
    __shared__ int   ri[128];

    const int tid = threadIdx.x;
    const int tx = tid & 15, ty = tid >> 4;
    const int r0 = blockIdx.x * 128;

    if (tid < 128) { rv[tid] = -1e30f; ri[tid] = 0; }

    for (int n0 = 0; n0 < KCODE; n0 += 128) {
        unsigned long long acc[8][4];
        #pragma unroll
        for (int i = 0; i < 8; i++)
            #pragma unroll
            for (int j = 0; j < 4; j++) acc[i][j] = 0ull;

        for (int k0 = 0; k0 < DIM; k0 += 16) {
            __syncthreads();
            #pragma unroll
            for (int u = 0; u < 2; u++) {
                int f4 = tid * 2 + u;          // 0..511
                int row = f4 >> 2, kq = f4 & 3;
                float4 v = *(const float4*)(g_flat + (size_t)(r0 + row) * DIM + k0 + kq * 4);
                As[kq * 4 + 0][row] = v.x; As[kq * 4 + 1][row] = v.y;
                As[kq * 4 + 2][row] = v.z; As[kq * 4 + 3][row] = v.w;
                float4 w = *(const float4*)(g_embn + (size_t)(n0 + row) * DIM + k0 + kq * 4);
                Bs[kq * 4 + 0][row] = w.x; Bs[kq * 4 + 1][row] = w.y;
                Bs[kq * 4 + 2][row] = w.z; Bs[kq * 4 + 3][row] = w.w;
            }
            __syncthreads();
            #pragma unroll
            for (int k = 0; k < 16; k++) {
                float4 a0 = *(const float4*)&As[k][ty * 8];
                float4 a1 = *(const float4*)&As[k][ty * 8 + 4];
                float4 b0 = *(const float4*)&Bs[k][tx * 8];
                float4 b1 = *(const float4*)&Bs[k][tx * 8 + 4];
                unsigned long long bp0, bp1, bp2, bp3;
                PACK2(bp0, b0.x, b0.y); PACK2(bp1, b0.z, b0.w);
                PACK2(bp2, b1.x, b1.y); PACK2(bp3, b1.z, b1.w);
                float av[8] = {a0.x, a0.y, a0.z, a0.w, a1.x, a1.y, a1.z, a1.w};
                #pragma unroll
                for (int i = 0; i < 8; i++) {
                    unsigned long long ad;
                    PACK2(ad, av[i], av[i]);
                    FMA2(acc[i][0], ad, bp0);
                    FMA2(acc[i][1], ad, bp1);
                    FMA2(acc[i][2], ad, bp2);
                    FMA2(acc[i][3], ad, bp3);
                }
            }
        }
        // local top-1 over this thread's 8 codes (ascending code order; strict > keeps lowest idx)
        #pragma unroll
        for (int i = 0; i < 8; i++) {
            float best = -1e30f; int bj = 0;
            #pragma unroll
            for (int j = 0; j < 4; j++) {
                float lo, hi;
                UNPACK2(lo, hi, acc[i][j]);
                if (lo > best) { best = lo; bj = 2 * j; }
                if (hi > best) { best = hi; bj = 2 * j + 1; }
            }
            cv[ty * 8 + i][tx] = best;
            ci[ty * 8 + i][tx] = n0 + tx * 8 + bj;
        }
        __syncthreads();
        if (tid < 128) {
            float best = rv[tid]; int bi = ri[tid];
            #pragma unroll
            for (int t = 0; t < 16; t++) {
                float v = cv[tid][t];
                if (v > best) { best = v; bi = ci[tid][t]; }
            }
            rv[tid] = best; ri[tid] = bi;
        }
        __syncthreads();
    }
    if (tid < 128) {
        g_idx[r0 + tid] = ri[tid];
        idx_out[r0 + tid] = (float)ri[tid];
    }
}

// gather quantized, quantized_st, loss partial, counts, dw scatter
__global__ void k_quant(const float* __restrict__ x, float* __restrict__ qout) {
    int row = blockIdx.x;
    int t = threadIdx.x;  // 128
    int idx = g_idx[row];
    float4 xv = ((const float4*)(x + (size_t)row * DIM))[t];
    float4 ev = ((const float4*)(g_embn + (size_t)idx * DIM))[t];
    float4 fv = ((const float4*)(g_flat + (size_t)row * DIM))[t];
    float4 q; float d, s = 0.f;
    d = ev.x - xv.x; q.x = xv.x + d; s += d * d;
    d = ev.y - xv.y; q.y = xv.y + d; s += d * d;
    d = ev.z - xv.z; q.z = xv.z + d; s += d * d;
    d = ev.w - xv.w; q.w = xv.w + d; s += d * d;
    ((float4*)(qout + (size_t)row * DIM))[t] = q;

    float* dwp = g_dw + (size_t)idx * DIM + t * 4;
    atomicAdd(dwp + 0, fv.x);
    atomicAdd(dwp + 1, fv.y);
    atomicAdd(dwp + 2, fv.z);
    atomicAdd(dwp + 3, fv.w);

    #pragma unroll
    for (int o = 16; o; o >>= 1) s += __shfl_xor_sync(0xFFFFFFFFu, s, o);
    __shared__ float wsum[4];
    if ((t & 31) == 0) wsum[t >> 5] = s;
    __syncthreads();
    if (t == 0) {
        atomicAdd(&g_loss, (double)(wsum[0] + wsum[1] + wsum[2] + wsum[3]));
        atomicAdd(&g_counts[idx], 1.0f);
    }
}

// cluster-size renorm + loss write; single block of 1024
__global__ void k_cs(const float* __restrict__ ema_cs,
                     float* __restrict__ out_cs, float* __restrict__ out_loss) {
    int t = threadIdx.x;
    float pre[8];
    float part = 0.f;
    #pragma unroll
    for (int u = 0; u < 8; u++) {
        int k = t + u * 1024;
        float p = ema_cs[k] * DECAY + ONE_MINUS_DECAY * g_counts[k];
        pre[u] = p;
        part += p;
    }
    #pragma unroll
    for (int o = 16; o; o >>= 1) part += __shfl_xor_sync(0xFFFFFFFFu, part, o);
    __shared__ float wsum[32];
    if ((t & 31) == 0) wsum[t >> 5] = part;
    __syncthreads();
    __shared__ float n_sh;
    if (t == 0) {
        float n = 0.f;
        for (int w = 0; w < 32; w++) n += wsum[w];
        n_sh = n;
    }
    __syncthreads();
    float n = n_sh;
    float denom = n + (float)KCODE * EPS;
    #pragma unroll
    for (int u = 0; u < 8; u++) {
        int k = t + u * 1024;
        float v = (pre[u] + EPS) / denom * n;
        out_cs[k] = v;
        g_newcs[k] = v;
    }
    if (t == 0) out_loss[0] = 0.25f * (float)(g_loss / (double)((size_t)NR * DIM));
}

// new_ema_w and new_embedding
// NOTE: out_w / out_emb are at ODD float offsets in the concatenated output
// buffer -> 4-byte aligned only. Vector loads (aligned sources), scalar stores.
__global__ void k_ema(const float* __restrict__ ema_w,
                      float* __restrict__ out_w, float* __restrict__ out_emb) {
    int i = blockIdx.x * blockDim.x + threadIdx.x;  // float4 index
    int tot4 = KCODE * DIM / 4;
    if (i >= tot4) return;
    float4 w = ((const float4*)ema_w)[i];
    float4 dv = ((const float4*)g_dw)[i];
    float4 nw = make_float4(w.x * DECAY + ONE_MINUS_DECAY * dv.x,
                            w.y * DECAY + ONE_MINUS_DECAY * dv.y,
                            w.z * DECAY + ONE_MINUS_DECAY * dv.z,
                            w.w * DECAY + ONE_MINUS_DECAY * dv.w);
    float* pw = out_w + (size_t)i * 4;
    pw[0] = nw.x; pw[1] = nw.y; pw[2] = nw.z; pw[3] = nw.w;
    int k = i / (DIM / 4);
    float cs = fmaxf(g_newcs[k], EPS);
    float inv = 1.0f / cs;
    float* pe = out_emb + (size_t)i * 4;
    pe[0] = nw.x * inv; pe[1] = nw.y * inv; pe[2] = nw.z * inv; pe[3] = nw.w * inv;
}

// ---------------- launch ----------------
extern "C" void kernel_launch(void* const* d_in, const int* in_sizes, int n_in,
                              void* d_out, int out_size) {
    const float* inputs    = (const float*)d_in[0];
    const float* embedding = (const float*)d_in[1];
    const float* ema_cs    = (const float*)d_in[2];
    const float* ema_w     = (const float*)d_in[3];
    float* out = (float*)d_out;

    k_zero<<<2048, 256>>>();
    k_norm<<<NR, 128>>>(inputs, 0);
    k_norm<<<KCODE, 128>>>(embedding, 1);
    k_argmax<<<NR / 128, 256>>>(out + OFF_IDX);
    k_quant<<<NR, 128>>>(inputs, out /* quantized_st at offset 0 */);
    k_cs<<<1, 1024>>>(ema_cs, out + OFF_CS, out + OFF_LOSS);
    k_ema<<<(KCODE * DIM / 4 + 255) / 256, 256>>>(ema_w, out + OFF_W, out + OFF_EMB);
}

// round 5
// speedup vs baseline: 7.6935x; 7.6935x over previous
#include <cuda_runtime.h>
#include <cuda_bf16.h>
#include <math.h>

#define NR   32768
#define DIM  512
#define KCODE 8192
#define DECAY 0.99f
#define ONE_MINUS_DECAY 0.01f
#define EPS 1e-5f
#define MARGIN 3.0e-3f
#define MAXCAND 32

// ---------------- scratch (__device__ globals; no allocation) ----------------
static __device__ __align__(256) float  g_flat[NR * DIM];      // normalized inputs fp32
static __device__ __align__(256) float  g_embn[KCODE * DIM];   // normalized embedding fp32
static __device__ __align__(256) __nv_bfloat16 g_flat_hi[NR * DIM];
static __device__ __align__(256) __nv_bfloat16 g_emb_hi[KCODE * DIM];
static __device__ int    g_idx[NR];
static __device__ int    g_clist[NR * MAXCAND];
static __device__ int    g_ccnt[NR];
static __device__ float  g_counts[KCODE];
static __device__ __align__(256) float  g_dw[KCODE * DIM];
static __device__ double g_loss;
static __device__ float  g_newcs[KCODE];

// ---------------- output layout (float32, concatenated in return order) -----
#define OFF_LOSS 16777216
#define OFF_IDX  16777217
#define OFF_CS   16809985
#define OFF_W    16818177
#define OFF_EMB  21012481

// ---------------- SMEM layout for argmax kernel ----------------
// A: 128 rows x 512 bf16 swizzled           [0, 131072)
// B: 2 x (128 codes x 64 bf16 swizzled)     [131072, 163840)
// D: 128 x 132 fp32 staging                 [163840, 231424)
#define S_A 0
#define S_B 131072
#define S_D 163840
#define SMEM_SZ 231424
#define DROW 132

__device__ __forceinline__ unsigned smem_u32(const void* p) {
    unsigned a;
    asm("{ .reg .u64 t; cvta.to.shared.u64 t, %1; cvt.u32.u64 %0, t; }" : "=r"(a) : "l"(p));
    return a;
}
__device__ __forceinline__ void cp16(unsigned dst, const void* src) {
    asm volatile("cp.async.cg.shared.global [%0], [%1], 16;" :: "r"(dst), "l"(src));
}
#define CP_COMMIT() asm volatile("cp.async.commit_group;" ::: "memory")
#define CP_WAIT1()  asm volatile("cp.async.wait_group 1;" ::: "memory")
#define CP_WAIT0()  asm volatile("cp.async.wait_group 0;" ::: "memory")

__device__ __forceinline__ void ldsm4(unsigned addr, unsigned& r0, unsigned& r1,
                                      unsigned& r2, unsigned& r3) {
    asm volatile("ldmatrix.sync.aligned.m8n8.x4.shared.b16 {%0,%1,%2,%3}, [%4];"
                 : "=r"(r0), "=r"(r1), "=r"(r2), "=r"(r3) : "r"(addr));
}
__device__ __forceinline__ void mma16816(float* d, const unsigned* a,
                                         unsigned b0, unsigned b1) {
    asm volatile("mma.sync.aligned.m16n8k16.row.col.f32.bf16.bf16.f32 "
                 "{%0,%1,%2,%3}, {%4,%5,%6,%7}, {%8,%9}, {%0,%1,%2,%3};"
                 : "+f"(d[0]), "+f"(d[1]), "+f"(d[2]), "+f"(d[3])
                 : "r"(a[0]), "r"(a[1]), "r"(a[2]), "r"(a[3]), "r"(b0), "r"(b1));
}

// swizzled byte offsets
__device__ __forceinline__ unsigned aoff(int row, int c) {   // A: 64 x 16B chunks/row
    return (unsigned)row * 1024u + (unsigned)((c & 56) | ((c ^ row) & 7)) * 16u;
}
__device__ __forceinline__ unsigned boff(int n, int cl) {    // B: 8 x 16B chunks/row
    return (unsigned)n * 128u + (unsigned)((cl ^ n) & 7) * 16u;
}

// ---------------- kernels ----------------
__global__ void k_zero() {
    int i = blockIdx.x * blockDim.x + threadIdx.x;
    int stride = gridDim.x * blockDim.x;
    float4 z = make_float4(0.f, 0.f, 0.f, 0.f);
    int tot4 = KCODE * DIM / 4;
    for (int j = i; j < tot4; j += stride) ((float4*)g_dw)[j] = z;
    for (int j = i; j < KCODE; j += stride) g_counts[j] = 0.f;
    if (i == 0) g_loss = 0.0;
}

// normalize rows; emit fp32 + bf16-hi
__global__ void k_norm(const float* __restrict__ src, int which) {
    int row = blockIdx.x;
    int t = threadIdx.x;  // 128 threads, 4 floats each
    const float4* s = (const float4*)(src + (size_t)row * DIM);
    float4 v = s[t];
    float ss = v.x * v.x + v.y * v.y + v.z * v.z + v.w * v.w;
    #pragma unroll
    for (int o = 16; o; o >>= 1) ss += __shfl_xor_sync(0xFFFFFFFFu, ss, o);
    __shared__ float wsum[4];
    if ((t & 31) == 0) wsum[t >> 5] = ss;
    __syncthreads();
    float tot = wsum[0] + wsum[1] + wsum[2] + wsum[3];
    float inv = 1.0f / fmaxf(sqrtf(tot), 1e-12f);
    float4 o4 = make_float4(v.x * inv, v.y * inv, v.z * inv, v.w * inv);
    float* dst = which ? g_embn : g_flat;
    __nv_bfloat16* dhi = which ? g_emb_hi : g_flat_hi;
    ((float4*)(dst + (size_t)row * DIM))[t] = o4;
    __nv_bfloat162 h0, h1;
    h0.x = __float2bfloat16(o4.x); h0.y = __float2bfloat16(o4.y);
    h1.x = __float2bfloat16(o4.z); h1.y = __float2bfloat16(o4.w);
    ((__nv_bfloat162*)(dhi + (size_t)row * DIM))[2 * t]     = h0;
    ((__nv_bfloat162*)(dhi + (size_t)row * DIM))[2 * t + 1] = h1;
}

// HMMA GEMM-argmax with margin candidate collection.
__global__ __launch_bounds__(256, 1) void k_argmax_mma() {
    extern __shared__ __align__(16) char smem[];
    const unsigned sb = smem_u32(smem);
    const int tid = threadIdx.x;
    const int lane = tid & 31;
    const int wid = tid >> 5;
    const int r0 = blockIdx.x * 128;

    // ---- load resident A_hi (swizzled) ----
    #pragma unroll 4
    for (int p = 0; p < 32; p++) {
        int g = p * 256 + tid;           // chunk id: 128 rows x 64 chunks
        int row = g >> 6, c = g & 63;
        uint4 v = *(const uint4*)(g_flat_hi + (size_t)(r0 + row) * DIM + c * 8);
        *(uint4*)(smem + S_A + aoff(row, c)) = v;
    }

    const int wm = (wid >> 1) * 32;      // warp m-origin (4 m-warps)
    const int wn = (wid & 1) * 64;       // warp n-origin (2 n-warps)
    const int rA0 = wm + (lane & 15);    // A ldmatrix row (i adds 16)
    const int ccA = lane >> 4;           // A k-half (16B units)

    float acc[2][8][4];
    #pragma unroll
    for (int i = 0; i < 2; i++)
        #pragma unroll
        for (int j = 0; j < 8; j++)
            #pragma unroll
            for (int q = 0; q < 4; q++) acc[i][j][q] = 0.f;

    float rMax = -1e30f;
    int cnt = 0;

    // ---- prefetch tile 0 ----
    {
        unsigned bb = sb + S_B;
        #pragma unroll
        for (int p = 0; p < 4; p++) {
            int n = p * 32 + wid * 4 + (lane >> 3);
            int cl = lane & 7;
            cp16(bb + boff(n, cl), g_emb_hi + (size_t)n * DIM + cl * 8);
        }
        CP_COMMIT();
    }

    for (int tI = 0; tI < 512; tI++) {
        const int nc = tI >> 3, kc = tI & 7;
        // prefetch next tile
        if (tI + 1 < 512) {
            int nn = (tI + 1) >> 3, nk = (tI + 1) & 7;
            unsigned bb = sb + S_B + ((tI + 1) & 1) * 16384;
            #pragma unroll
            for (int p = 0; p < 4; p++) {
                int n = p * 32 + wid * 4 + (lane >> 3);
                int cl = lane & 7;
                cp16(bb + boff(n, cl),
                     g_emb_hi + (size_t)(nn * 128 + n) * DIM + nk * 64 + cl * 8);
            }
            CP_COMMIT();
            CP_WAIT1();
        } else {
            CP_WAIT0();
        }
        __syncthreads();

        const unsigned Bb = sb + S_B + (tI & 1) * 16384;
        #pragma unroll
        for (int ks = 0; ks < 4; ks++) {
            const int c16 = (kc * 4 + ks) * 2;         // A chunk base (16B units)
            unsigned a[2][4];
            #pragma unroll
            for (int i = 0; i < 2; i++)
                ldsm4(sb + S_A + aoff(rA0 + i * 16, c16 + ccA),
                      a[i][0], a[i][1], a[i][2], a[i][3]);
            unsigned bb[4][4];
            #pragma unroll
            for (int j = 0; j < 4; j++) {
                int n = wn + j * 16 + (lane & 15);
                ldsm4(Bb + boff(n, ks * 2 + (lane >> 4)),
                      bb[j][0], bb[j][1], bb[j][2], bb[j][3]);
            }
            #pragma unroll
            for (int i = 0; i < 2; i++)
                #pragma unroll
                for (int j8 = 0; j8 < 8; j8++) {
                    int jj = j8 >> 1, s = j8 & 1;
                    mma16816(acc[i][j8], a[i], bb[jj][s], bb[jj][s + 2]);
                }
        }

        if (kc == 7) {
            // ---- epilogue for this n-chunk: stage D, scan rows ----
            float* D = (float*)(smem + S_D);
            const int mr = wm + (lane >> 2);
            const int ncl = wn + (lane & 3) * 2;
            #pragma unroll
            for (int i = 0; i < 2; i++) {
                #pragma unroll
                for (int j8 = 0; j8 < 8; j8++) {
                    int col = ncl + j8 * 8;
                    *(float2*)&D[(mr + i * 16) * DROW + col] =
                        make_float2(acc[i][j8][0], acc[i][j8][1]);
                    *(float2*)&D[(mr + i * 16 + 8) * DROW + col] =
                        make_float2(acc[i][j8][2], acc[i][j8][3]);
                    acc[i][j8][0] = acc[i][j8][1] = acc[i][j8][2] = acc[i][j8][3] = 0.f;
                }
            }
            __syncthreads();
            if (tid < 128) {
                const float4* Dr = (const float4*)&D[tid * DROW];
                float cm = -1e30f;
                #pragma unroll 8
                for (int q = 0; q < 32; q++) {
                    float4 v = Dr[q];
                    cm = fmaxf(cm, fmaxf(fmaxf(v.x, v.y), fmaxf(v.z, v.w)));
                }
                float nm = fmaxf(rMax, cm);
                if (cm >= nm - MARGIN) {
                    float th = nm - MARGIN;
                    const float* Ds = &D[tid * DROW];
                    for (int j = 0; j < 128; j++) {
                        if (Ds[j] >= th && cnt < MAXCAND)
                            g_clist[(size_t)(r0 + tid) * MAXCAND + cnt++] = nc * 128 + j;
                    }
                }
                rMax = nm;
            }
            __syncthreads();
        } else {
            __syncthreads();
        }
    }

    if (tid < 128) g_ccnt[r0 + tid] = cnt;
}

// exact fp32 rescore over the candidate list (distance = 1 - dot, lowest index wins ties)
__global__ void k_rescore(float* __restrict__ idx_out) {
    int row = blockIdx.x;
    int t = threadIdx.x;  // 128
    int cnt = g_ccnt[row];
    __shared__ float sred[4];
    __shared__ float bestd;
    __shared__ int   besti;
    if (t == 0) { bestd = 1e30f; besti = 0; }
    __syncthreads();
    float4 f = ((const float4*)(g_flat + (size_t)row * DIM))[t];
    for (int c = 0; c < cnt; c++) {
        int idx = g_clist[(size_t)row * MAXCAND + c];
        float4 e = ((const float4*)(g_embn + (size_t)idx * DIM))[t];
        float d = f.x * e.x + f.y * e.y + f.z * e.z + f.w * e.w;
        #pragma unroll
        for (int o = 16; o; o >>= 1) d += __shfl_xor_sync(0xFFFFFFFFu, d, o);
        if ((t & 31) == 0) sred[t >> 5] = d;
        __syncthreads();
        if (t == 0) {
            float dot = sred[0] + sred[1] + sred[2] + sred[3];
            float dist = 1.0f - dot;
            if (dist < bestd) { bestd = dist; besti = idx; }   // list ascending -> ties keep lower idx
        }
        __syncthreads();
    }
    if (t == 0) {
        g_idx[row] = besti;
        idx_out[row] = (float)besti;
    }
}

// gather quantized_st, loss partial, counts, dw scatter
__global__ void k_quant(const float* __restrict__ x, float* __restrict__ qout) {
    int row = blockIdx.x;
    int t = threadIdx.x;  // 128
    int idx = g_idx[row];
    float4 xv = ((const float4*)(x + (size_t)row * DIM))[t];
    float4 ev = ((const float4*)(g_embn + (size_t)idx * DIM))[t];
    float4 fv = ((const float4*)(g_flat + (size_t)row * DIM))[t];
    float4 q; float d, s = 0.f;
    d = ev.x - xv.x; q.x = xv.x + d; s += d * d;
    d = ev.y - xv.y; q.y = xv.y + d; s += d * d;
    d = ev.z - xv.z; q.z = xv.z + d; s += d * d;
    d = ev.w - xv.w; q.w = xv.w + d; s += d * d;
    ((float4*)(qout + (size_t)row * DIM))[t] = q;

    float* dwp = g_dw + (size_t)idx * DIM + t * 4;
    atomicAdd(dwp + 0, fv.x);
    atomicAdd(dwp + 1, fv.y);
    atomicAdd(dwp + 2, fv.z);
    atomicAdd(dwp + 3, fv.w);

    #pragma unroll
    for (int o = 16; o; o >>= 1) s += __shfl_xor_sync(0xFFFFFFFFu, s, o);
    __shared__ float wsum[4];
    if ((t & 31) == 0) wsum[t >> 5] = s;
    __syncthreads();
    if (t == 0) {
        atomicAdd(&g_loss, (double)(wsum[0] + wsum[1] + wsum[2] + wsum[3]));
        atomicAdd(&g_counts[idx], 1.0f);
    }
}

__global__ void k_cs(const float* __restrict__ ema_cs,
                     float* __restrict__ out_cs, float* __restrict__ out_loss) {
    int t = threadIdx.x;
    float pre[8];
    float part = 0.f;
    #pragma unroll
    for (int u = 0; u < 8; u++) {
        int k = t + u * 1024;
        float p = ema_cs[k] * DECAY + ONE_MINUS_DECAY * g_counts[k];
        pre[u] = p;
        part += p;
    }
    #pragma unroll
    for (int o = 16; o; o >>= 1) part += __shfl_xor_sync(0xFFFFFFFFu, part, o);
    __shared__ float wsum[32];
    if ((t & 31) == 0) wsum[t >> 5] = part;
    __syncthreads();
    __shared__ float n_sh;
    if (t == 0) {
        float n = 0.f;
        for (int w = 0; w < 32; w++) n += wsum[w];
        n_sh = n;
    }
    __syncthreads();
    float n = n_sh;
    float denom = n + (float)KCODE * EPS;
    #pragma unroll
    for (int u = 0; u < 8; u++) {
        int k = t + u * 1024;
        float v = (pre[u] + EPS) / denom * n;
        out_cs[k] = v;
        g_newcs[k] = v;
    }
    if (t == 0) out_loss[0] = 0.25f * (float)(g_loss / (double)((size_t)NR * DIM));
}

// new_ema_w / new_embedding (dest at ODD float offsets -> scalar stores)
__global__ void k_ema(const float* __restrict__ ema_w,
                      float* __restrict__ out_w, float* __restrict__ out_emb) {
    int i = blockIdx.x * blockDim.x + threadIdx.x;
    int tot4 = KCODE * DIM / 4;
    if (i >= tot4) return;
    float4 w = ((const float4*)ema_w)[i];
    float4 dv = ((const float4*)g_dw)[i];
    float4 nw = make_float4(w.x * DECAY + ONE_MINUS_DECAY * dv.x,
                            w.y * DECAY + ONE_MINUS_DECAY * dv.y,
                            w.z * DECAY + ONE_MINUS_DECAY * dv.z,
                            w.w * DECAY + ONE_MINUS_DECAY * dv.w);
    float* pw = out_w + (size_t)i * 4;
    pw[0] = nw.x; pw[1] = nw.y; pw[2] = nw.z; pw[3] = nw.w;
    int k = i / (DIM / 4);
    float cs = fmaxf(g_newcs[k], EPS);
    float inv = 1.0f / cs;
    float* pe = out_emb + (size_t)i * 4;
    pe[0] = nw.x * inv; pe[1] = nw.y * inv; pe[2] = nw.z * inv; pe[3] = nw.w * inv;
}

// ---------------- launch ----------------
extern "C" void kernel_launch(void* const* d_in, const int* in_sizes, int n_in,
                              void* d_out, int out_size) {
    const float* inputs    = (const float*)d_in[0];
    const float* embedding = (const float*)d_in[1];
    const float* ema_cs    = (const float*)d_in[2];
    const float* ema_w     = (const float*)d_in[3];
    float* out = (float*)d_out;

    cudaFuncSetAttribute(k_argmax_mma, cudaFuncAttributeMaxDynamicSharedMemorySize, SMEM_SZ);

    k_zero<<<2048, 256>>>();
    k_norm<<<NR, 128>>>(inputs, 0);
    k_norm<<<KCODE, 128>>>(embedding, 1);
    k_argmax_mma<<<NR / 128, 256, SMEM_SZ>>>();
    k_rescore<<<NR, 128>>>(out + OFF_IDX);
    k_quant<<<NR, 128>>>(inputs, out);
    k_cs<<<1, 1024>>>(ema_cs, out + OFF_CS, out + OFF_LOSS);
    k_ema<<<(KCODE * DIM / 4 + 255) / 256, 256>>>(ema_w, out + OFF_W, out + OFF_EMB);
}